// round 1
// baseline (speedup 1.0000x reference)
#include <cuda_runtime.h>
#include <cstdint>

// Problem constants
#define B_  512
#define T_  512
#define NQ_ 1000
#define K_  5
#define M_  50
#define DK_ 64
#define DV_ 256
#define DF_ 50
#define BT_ (B_*T_)   // 262144

// ---------------- scratch (device globals; no allocation allowed) ----------------
__device__ __align__(16) float g_Tw   [(NQ_+1)*M_];      // softmaxed attention per q
__device__ __align__(16) float g_Tsq  [(NQ_+1)*DF_];     // qe @ summary_W[256:]
__device__ __align__(16) float g_Tbeta[(NQ_+1)*4];       // qe @ thresh_W + b
__device__ __align__(16) float g_Tdisc[(NQ_+1)];         // qe @ disc_W[50:] + b
__device__ __align__(16) float g_Tcorn[(NQ_+1)*4];       // qe @ corn_W[50:] + b
__device__ __align__(16) float g_E1[NQ_*DV_], g_E2[NQ_*DV_];
__device__ __align__(16) float g_A1[NQ_*DV_], g_A2[NQ_*DV_];
__device__ __align__(16) float g_be[DV_], g_ba[DV_];
__device__ __align__(16) float g_Te[(NQ_+1)*K_*DV_];     // sigmoid(erase pre) per (q,r)
__device__ __align__(16) float g_Ta[(NQ_+1)*K_*DV_];     // tanh(add pre)  per (q,r)
__device__ __align__(16) float g_reads  [BT_*DV_];       // 268 MB
__device__ __align__(16) float g_summary[BT_*DF_];       // 52 MB

__device__ __forceinline__ float sigmoidf_(float x) { return 1.f/(1.f+expf(-x)); }

// ---------------- P0: effective biases  be = value_b@We + erase_b, etc ----------------
__global__ void p0_bias(const float* __restrict__ vb,
                        const float* __restrict__ We, const float* __restrict__ eb,
                        const float* __restrict__ Wa, const float* __restrict__ ab) {
    __shared__ float svb[DV_];
    int v = threadIdx.x;
    svb[v] = vb[v];
    __syncthreads();
    float e = eb[v], a = ab[v];
    for (int k = 0; k < DV_; k++) {
        float x = svb[k];
        e = fmaf(x, We[k*DV_+v], e);
        a = fmaf(x, Wa[k*DV_+v], a);
    }
    g_be[v] = e; g_ba[v] = a;
}

// ---------------- P1: per-question tables (1001 blocks x 128 threads) ----------------
__global__ void p1_qtables(const float* __restrict__ qW, const float* __restrict__ Mk,
                           const float* __restrict__ sW,
                           const float* __restrict__ tW, const float* __restrict__ tb,
                           const float* __restrict__ dW, const float* __restrict__ db,
                           const float* __restrict__ cW, const float* __restrict__ cb) {
    __shared__ float qe[DK_];
    __shared__ float wl[M_];
    __shared__ float red[2];
    int q = blockIdx.x, tid = threadIdx.x;
    if (tid < DK_) qe[tid] = qW[q*DK_ + tid];
    __syncthreads();
    if (tid < 50) {                       // attention logits
        float acc = 0.f;
        const float* mk = Mk + tid*DK_;
        #pragma unroll 16
        for (int k = 0; k < DK_; k++) acc = fmaf(qe[k], mk[k], acc);
        wl[tid] = acc;
    } else if (tid < 100) {               // summary qe-part
        int j = tid - 50; float acc = 0.f;
        for (int k = 0; k < DK_; k++) acc = fmaf(qe[k], sW[(DV_+k)*DF_ + j], acc);
        g_Tsq[q*DF_ + j] = acc;
    } else if (tid < 104) {               // betas
        int c = tid - 100; float acc = tb[c];
        for (int k = 0; k < DK_; k++) acc = fmaf(qe[k], tW[k*4 + c], acc);
        g_Tbeta[q*4 + c] = acc;
    } else if (tid == 104) {              // disc qe-part
        float acc = db[0];
        for (int k = 0; k < DK_; k++) acc = fmaf(qe[k], dW[50 + k], acc);
        g_Tdisc[q] = acc;
    } else if (tid < 109) {               // corn qe-part
        int c = tid - 105; float acc = cb[c];
        for (int k = 0; k < DK_; k++) acc = fmaf(qe[k], cW[(50+k)*4 + c], acc);
        g_Tcorn[q*4 + c] = acc;
    }
    __syncthreads();
    if (tid == 0) {
        float mx = wl[0];
        for (int m = 1; m < M_; m++) mx = fmaxf(mx, wl[m]);
        red[0] = mx;
    }
    __syncthreads();
    if (tid < M_) wl[tid] = expf(wl[tid] - red[0]);
    __syncthreads();
    if (tid == 0) {
        float s = 0.f;
        for (int m = 0; m < M_; m++) s += wl[m];
        red[1] = 1.f / s;
    }
    __syncthreads();
    if (tid < M_) g_Tw[q*M_ + tid] = wl[tid] * red[1];
}

// ---------------- P2: E/A tables  value_W @ {erase_W, add_W}  (125 blocks x 256) ----------------
__global__ void p2_etables(const float* __restrict__ vW,
                           const float* __restrict__ We, const float* __restrict__ Wa) {
    __shared__ float vr1[8][DV_];
    __shared__ float vr2[8][DV_];
    int i0 = blockIdx.x * 8, tid = threadIdx.x;
    #pragma unroll
    for (int i = 0; i < 8; i++) {
        vr1[i][tid] = vW[(i0+i)*DV_ + tid];
        vr2[i][tid] = vW[(NQ_ + i0+i)*DV_ + tid];
    }
    __syncthreads();
    float e1[8] = {0}, e2[8] = {0}, a1[8] = {0}, a2[8] = {0};
    int v = tid;
    for (int k = 0; k < DV_; k++) {
        float we = We[k*DV_ + v];
        float wa = Wa[k*DV_ + v];
        #pragma unroll
        for (int i = 0; i < 8; i++) {
            float x1 = vr1[i][k], x2 = vr2[i][k];
            e1[i] = fmaf(x1, we, e1[i]); e2[i] = fmaf(x2, we, e2[i]);
            a1[i] = fmaf(x1, wa, a1[i]); a2[i] = fmaf(x2, wa, a2[i]);
        }
    }
    #pragma unroll
    for (int i = 0; i < 8; i++) {
        g_E1[(i0+i)*DV_ + v] = e1[i]; g_E2[(i0+i)*DV_ + v] = e2[i];
        g_A1[(i0+i)*DV_ + v] = a1[i]; g_A2[(i0+i)*DV_ + v] = a2[i];
    }
}

// ---------------- P3: activation tables per (q,r)  (5005 blocks x 256) ----------------
__global__ void p3_acts() {
    int q = blockIdx.x / K_, r = blockIdx.x % K_;
    int v = threadIdx.x;
    float rs = (float)r * 0.25f;
    float pe = 0.f, pa = 0.f;
    if (q > 0) {
        int idx = q - 1;
        pe = fmaf(rs, g_E2[idx*DV_ + v], g_E1[idx*DV_ + v]);
        pa = fmaf(rs, g_A2[idx*DV_ + v], g_A1[idx*DV_ + v]);
    }
    pe += g_be[v]; pa += g_ba[v];
    int base = (q*K_ + r)*DV_ + v;
    g_Te[base] = sigmoidf_(pe);
    g_Ta[base] = tanhf(pa);
}

// ---------------- Scan: grid (2, 512), 128 threads; Mv in registers ----------------
__global__ __launch_bounds__(128) void scan_kernel(const int* __restrict__ qd,
                                                   const int* __restrict__ rd,
                                                   const float* __restrict__ Mv0) {
    __shared__ __align__(16) float w_s[52];
    int b   = blockIdx.y;
    int vb  = blockIdx.x;
    int tid = threadIdx.x;
    int v   = vb*128 + tid;
    float Mv[52];
    #pragma unroll
    for (int m = 0; m < M_; m++) Mv[m] = Mv0[m*DV_ + v];
    Mv[50] = 0.f; Mv[51] = 0.f;
    if (tid < 2) w_s[50 + tid] = 0.f;
    const int bT = b * T_;
    float* rout = g_reads + (size_t)bT * DV_ + v;
    int qcur = __ldg(qd + bT), rcur = __ldg(rd + bT);
    for (int t = 0; t < T_; t++) {
        __syncthreads();                       // protect w_s from previous iteration
        if (tid < M_) w_s[tid] = g_Tw[qcur*M_ + tid];
        int base = (qcur*K_ + rcur)*DV_ + v;
        float e = __ldg(g_Te + base);
        float a = __ldg(g_Ta + base);
        if (t + 1 < T_) {                      // prefetch next q,r
            qcur = __ldg(qd + bT + t + 1);
            rcur = __ldg(rd + bT + t + 1);
        }
        __syncthreads();
        float acc = 0.f;
        float na = -a;
        #pragma unroll
        for (int j = 0; j < 13; j++) {
            float4 w4 = *(const float4*)&w_s[j*4];
            {
                float old = Mv[4*j+0]; acc = fmaf(w4.x, old, acc);
                float t1 = fmaf(old, e, na); Mv[4*j+0] = fmaf(-w4.x, t1, old);
            }
            {
                float old = Mv[4*j+1]; acc = fmaf(w4.y, old, acc);
                float t1 = fmaf(old, e, na); Mv[4*j+1] = fmaf(-w4.y, t1, old);
            }
            {
                float old = Mv[4*j+2]; acc = fmaf(w4.z, old, acc);
                float t1 = fmaf(old, e, na); Mv[4*j+2] = fmaf(-w4.z, t1, old);
            }
            {
                float old = Mv[4*j+3]; acc = fmaf(w4.w, old, acc);
                float t1 = fmaf(old, e, na); Mv[4*j+3] = fmaf(-w4.w, t1, old);
            }
        }
        rout[(size_t)t * DV_] = acc;
    }
}

// ---------------- Summary GEMM: reads[BT,256] @ summary_W[:256,:50], +Tsq, tanh ----------------
#define GBM 64
#define GBN 64
#define GBK 16
__global__ __launch_bounds__(256) void summary_gemm(const float* __restrict__ sW,
                                                    const float* __restrict__ sb,
                                                    const int* __restrict__ qd) {
    __shared__ __align__(16) float As[GBK][GBM];
    __shared__ __align__(16) float Bs[GBK][GBN];
    int tid = threadIdx.x;
    int brow = blockIdx.x * GBM;
    int tx = tid & 15, ty = tid >> 4;
    int lrow = tid >> 2;            // 0..63
    int lk4  = (tid & 3) * 4;       // 0,4,8,12
    int bk   = tid >> 4;            // 0..15
    int bj4  = (tid & 15) * 4;      // 0..60
    float acc[4][4] = {};
    for (int k0 = 0; k0 < DV_; k0 += GBK) {
        float4 av = *(const float4*)(g_reads + (size_t)(brow + lrow)*DV_ + k0 + lk4);
        As[lk4+0][lrow] = av.x; As[lk4+1][lrow] = av.y;
        As[lk4+2][lrow] = av.z; As[lk4+3][lrow] = av.w;
        int krow = k0 + bk;
        #pragma unroll
        for (int jj = 0; jj < 4; jj++) {
            int j = bj4 + jj;
            Bs[bk][j] = (j < DF_) ? sW[krow*DF_ + j] : 0.f;
        }
        __syncthreads();
        #pragma unroll
        for (int k = 0; k < GBK; k++) {
            float4 a4 = *(const float4*)&As[k][ty*4];
            float4 b4 = *(const float4*)&Bs[k][tx*4];
            float ar[4] = {a4.x, a4.y, a4.z, a4.w};
            float br[4] = {b4.x, b4.y, b4.z, b4.w};
            #pragma unroll
            for (int i = 0; i < 4; i++)
                #pragma unroll
                for (int j = 0; j < 4; j++)
                    acc[i][j] = fmaf(ar[i], br[j], acc[i][j]);
        }
        __syncthreads();
    }
    #pragma unroll
    for (int i = 0; i < 4; i++) {
        int row = brow + ty*4 + i;
        int q = qd[row];
        #pragma unroll
        for (int j = 0; j < 4; j++) {
            int jj = tx*4 + j;
            if (jj < DF_)
                g_summary[(size_t)row*DF_ + jj] =
                    tanhf(acc[i][j] + g_Tsq[q*DF_ + jj] + sb[jj]);
        }
    }
}

// ---------------- Heads: theta/betas/alpha/probs/logits  (2048 blocks x 128) ----------------
__global__ __launch_bounds__(128) void heads_kernel(const int* __restrict__ qd,
                                                    const float* __restrict__ abW,
                                                    const float* __restrict__ abB,
                                                    const float* __restrict__ dW,
                                                    const float* __restrict__ cW,
                                                    float* __restrict__ out) {
    __shared__ float sS[128*DF_];
    __shared__ float sAb[DF_], sDw[DF_], sCw[DF_*4];
    int tid = threadIdx.x;
    int base = blockIdx.x * 128;
    for (int idx = tid; idx < 128*DF_; idx += 128)
        sS[idx] = g_summary[(size_t)base*DF_ + idx];
    if (tid < DF_) { sAb[tid] = abW[tid]; sDw[tid] = dW[tid]; }
    for (int idx = tid; idx < DF_*4; idx += 128) sCw[idx] = cW[idx];
    __syncthreads();
    int i = base + tid;
    int q = qd[i];
    float th = 0.f, ap = 0.f, l0 = 0.f, l1 = 0.f, l2 = 0.f, l3 = 0.f;
    #pragma unroll 10
    for (int k = 0; k < DF_; k++) {
        float s = sS[tid*DF_ + k];
        th = fmaf(s, sAb[k], th);
        ap = fmaf(s, sDw[k], ap);
        l0 = fmaf(s, sCw[k*4+0], l0);
        l1 = fmaf(s, sCw[k*4+1], l1);
        l2 = fmaf(s, sCw[k*4+2], l2);
        l3 = fmaf(s, sCw[k*4+3], l3);
    }
    float theta = (th + abB[0]) * 3.0f;
    ap += g_Tdisc[q];
    float alpha = (ap > 20.f) ? ap : log1pf(expf(ap));
    float4 tc = *(const float4*)&g_Tcorn[q*4];
    l0 += tc.x; l1 += tc.y; l2 += tc.z; l3 += tc.w;
    float cp0 = sigmoidf_(l0);
    float cp1 = cp0 * sigmoidf_(l1);
    float cp2 = cp1 * sigmoidf_(l2);
    float cp3 = cp2 * sigmoidf_(l3);
    const int BT = BT_;
    out[i] = theta;
    *(float4*)&out[BT + 4*i] = *(const float4*)&g_Tbeta[q*4];
    out[5*BT + i] = alpha;
    float* pp = out + 6*BT + 5*i;
    pp[0] = 1.f - cp0; pp[1] = cp0 - cp1; pp[2] = cp1 - cp2;
    pp[3] = cp2 - cp3; pp[4] = cp3;
    *(float4*)&out[11*BT + 4*i] = make_float4(l0, l1, l2, l3);
}

// ---------------- launch ----------------
extern "C" void kernel_launch(void* const* d_in, const int* in_sizes, int n_in,
                              void* d_out, int out_size) {
    const int*   q_data    = (const int*)  d_in[0];
    const int*   r_data    = (const int*)  d_in[1];
    const float* q_embed_W = (const float*)d_in[2];
    const float* Mk        = (const float*)d_in[3];
    const float* Mv0       = (const float*)d_in[4];
    const float* value_W   = (const float*)d_in[5];
    const float* value_b   = (const float*)d_in[6];
    const float* erase_W   = (const float*)d_in[7];
    const float* erase_b   = (const float*)d_in[8];
    const float* add_W     = (const float*)d_in[9];
    const float* add_b     = (const float*)d_in[10];
    const float* summary_W = (const float*)d_in[11];
    const float* summary_b = (const float*)d_in[12];
    const float* ability_W = (const float*)d_in[13];
    const float* ability_b = (const float*)d_in[14];
    const float* thresh_W  = (const float*)d_in[15];
    const float* thresh_b  = (const float*)d_in[16];
    const float* disc_W    = (const float*)d_in[17];
    const float* disc_b    = (const float*)d_in[18];
    const float* corn_W    = (const float*)d_in[19];
    const float* corn_b    = (const float*)d_in[20];
    float* out = (float*)d_out;

    p0_bias<<<1, 256>>>(value_b, erase_W, erase_b, add_W, add_b);
    p1_qtables<<<NQ_+1, 128>>>(q_embed_W, Mk, summary_W,
                               thresh_W, thresh_b, disc_W, disc_b, corn_W, corn_b);
    p2_etables<<<NQ_/8, 256>>>(value_W, erase_W, add_W);
    p3_acts<<<(NQ_+1)*K_, 256>>>();
    scan_kernel<<<dim3(2, B_), 128>>>(q_data, r_data, Mv0);
    summary_gemm<<<BT_/GBM, 256>>>(summary_W, summary_b, q_data);
    heads_kernel<<<BT_/128, 128>>>(q_data, ability_W, ability_b,
                                   disc_W, corn_W, out);
}